// round 1
// baseline (speedup 1.0000x reference)
#include <cuda_runtime.h>
#include <cstdint>

#define B_  8
#define D_  256
#define T_  2048
#define K_  8192
#define BT_ (B_ * T_)          // 16384 rows of z_flat
#define ZQ_ELEMS (BT_ * D_)    // 4194304

// ---------------- device scratch (no allocations allowed) ----------------
__device__ unsigned long long g_best[BT_];  // packed (orderedDist<<32 | idx)
__device__ float  g_s1[BT_];                // |z_m|^2 (fp32, rounded from fp64)
__device__ float  g_s2[K_];                 // |c_n|^2
__device__ double g_loss;

// ---------------- init ----------------
__global__ void init_kernel() {
    int i = blockIdx.x * blockDim.x + threadIdx.x;
    if (i < BT_) g_best[i] = 0xFFFFFFFFFFFFFFFFULL;
    if (i == 0)  g_loss = 0.0;
}

// ---------------- |c|^2 : one warp per code ----------------
__global__ void s2_kernel(const float* __restrict__ cb) {
    int warp = (blockIdx.x * blockDim.x + threadIdx.x) >> 5;
    int lane = threadIdx.x & 31;
    if (warp >= K_) return;
    const float* row = cb + (size_t)warp * D_;
    double s = 0.0;
    for (int d = lane; d < D_; d += 32) { float v = row[d]; s += (double)v * v; }
    #pragma unroll
    for (int o = 16; o; o >>= 1) s += __shfl_xor_sync(0xffffffffu, s, o);
    if (lane == 0) g_s2[warp] = (float)s;
}

// ---------------- |z_m|^2 : block handles 32 rows (same b, consecutive t) ----
__global__ void s1_kernel(const float* __restrict__ z) {
    __shared__ double sm[8][33];
    int m0 = blockIdx.x * 32;
    int b  = m0 >> 11;
    int t0 = m0 & 2047;
    int tt   = threadIdx.x & 31;   // t within chunk (coalesced)
    int part = threadIdx.x >> 5;   // d-partition 0..7
    double s = 0.0;
    #pragma unroll 4
    for (int di = 0; di < 32; di++) {
        int d = part * 32 + di;
        float v = z[((size_t)b * D_ + d) * T_ + t0 + tt];
        s += (double)v * v;
    }
    sm[part][tt] = s;
    __syncthreads();
    if (part == 0) {
        double tot = 0.0;
        #pragma unroll
        for (int p = 0; p < 8; p++) tot += sm[p][tt];
        g_s1[m0 + tt] = (float)tot;
    }
}

// ---------------- distance GEMM + fused argmin ----------------
// Tiles: BM=128 rows x BN=128 codes, BK=16 over D=256. 256 threads, 8x8 microtile.
#define BM 128
#define BN 128
#define BK 16

__global__ void __launch_bounds__(256, 2)
dist_argmin_kernel(const float* __restrict__ z, const float* __restrict__ cb) {
    __shared__ float As[BK][BM];
    __shared__ float Bs[BK][BN + 4];

    int tid = threadIdx.x;
    int tx = tid & 15, ty = tid >> 4;
    int m0 = blockIdx.y * BM;        // row-block: fixed b, contiguous t
    int n0 = blockIdx.x * BN;
    int b  = m0 >> 11;
    int t0 = m0 & 2047;

    const float* zb = z + (size_t)b * D_ * T_ + t0;

    float acc[8][8];
    #pragma unroll
    for (int i = 0; i < 8; i++)
        #pragma unroll
        for (int j = 0; j < 8; j++) acc[i][j] = 0.0f;

    for (int d0 = 0; d0 < D_; d0 += BK) {
        // A tile: 128 (t) x 16 (d). float4 along t -> fully coalesced.
        #pragma unroll
        for (int j = 0; j < 2; j++) {
            int idx = tid + j * 256;        // float4 index 0..511
            int di  = idx >> 5;             // 0..15
            int m4  = idx & 31;             // 0..31 (x4 floats)
            float4 v = *reinterpret_cast<const float4*>(
                zb + (size_t)(d0 + di) * T_ + m4 * 4);
            *reinterpret_cast<float4*>(&As[di][m4 * 4]) = v;
        }
        // B tile: 128 codes x 16 d, transposed into Bs[d][n].
        #pragma unroll
        for (int j = 0; j < 2; j++) {
            int idx = tid + j * 256;
            int n   = idx >> 2;             // 0..127
            int d4  = idx & 3;              // 0..3 (x4 floats)
            float4 v = *reinterpret_cast<const float4*>(
                cb + (size_t)(n0 + n) * D_ + d0 + d4 * 4);
            Bs[d4 * 4 + 0][n] = v.x;
            Bs[d4 * 4 + 1][n] = v.y;
            Bs[d4 * 4 + 2][n] = v.z;
            Bs[d4 * 4 + 3][n] = v.w;
        }
        __syncthreads();
        #pragma unroll
        for (int kk = 0; kk < BK; kk++) {
            float ra[8], rb[8];
            #pragma unroll
            for (int i = 0; i < 8; i++) ra[i] = As[kk][ty * 8 + i];
            #pragma unroll
            for (int j = 0; j < 8; j++) rb[j] = Bs[kk][tx * 8 + j];
            #pragma unroll
            for (int i = 0; i < 8; i++)
                #pragma unroll
                for (int j = 0; j < 8; j++)
                    acc[i][j] = fmaf(ra[i], rb[j], acc[i][j]);
        }
        __syncthreads();
    }

    // Epilogue: replicate reference rounding  f = fl(fl(s1 - 2*dot) + s2).
    // (2*dot is exact in fp32; FMA contraction of s1-2*dot rounds identically.)
    #pragma unroll
    for (int i = 0; i < 8; i++) {
        int m = m0 + ty * 8 + i;
        float s1 = g_s1[m];
        unsigned long long best = 0xFFFFFFFFFFFFFFFFULL;
        #pragma unroll
        for (int j = 0; j < 8; j++) {
            int n = n0 + tx * 8 + j;
            float f = (s1 - 2.0f * acc[i][j]) + g_s2[n];
            unsigned u = __float_as_uint(f);
            u = (u & 0x80000000u) ? ~u : (u | 0x80000000u);  // order-preserving
            unsigned long long key =
                ((unsigned long long)u << 32) | (unsigned)n;  // tie -> lower idx
            best = min(best, key);
        }
        // reduce across the 16 threads (tx) sharing this row; xor<16 stays in group
        #pragma unroll
        for (int o = 8; o; o >>= 1) {
            unsigned long long other = __shfl_xor_sync(0xffffffffu, best, o);
            best = min(best, other);
        }
        if (tx == 0) atomicMin(&g_best[m], best);
    }
}

// ---------------- gather z_q_st (transposed), indices, loss ----------------
__global__ void gather_kernel(const float* __restrict__ z,
                              const float* __restrict__ cb,
                              float* __restrict__ out, int out_size) {
    __shared__ float sm[32][257];
    __shared__ int   sidx[32];
    __shared__ double ssum[8];
    int m0 = blockIdx.x * 32;        // 32 consecutive (b,t) rows, same b
    int b  = m0 >> 11;
    int t0 = m0 & 2047;
    int tid = threadIdx.x;

    if (tid < 32) {
        int idx = (int)(g_best[m0 + tid] & 0xFFFFFFFFULL);
        sidx[tid] = idx;
        if (out_size >= ZQ_ELEMS + BT_)
            out[ZQ_ELEMS + m0 + tid] = (float)idx;   // indices as float
    }
    __syncthreads();

    // stage 32 codebook rows into smem (coalesced 1KB reads)
    for (int r = 0; r < 32; r++)
        sm[r][tid] = cb[(size_t)sidx[r] * D_ + tid];
    __syncthreads();

    // write z_q_st in (B,D,T) layout; coalesced along t. Replicate STE rounding.
    int tt = tid & 31;   // t lane
    int dp = tid >> 5;   // d partition 0..7
    double lsum = 0.0;
    #pragma unroll 4
    for (int it = 0; it < 32; it++) {
        int d = dp * 32 + it;
        size_t oi = ((size_t)b * D_ + d) * T_ + t0 + tt;
        float zq = sm[tt][d];          // conflict-free: bank = (tt + d) % 32
        float zv = z[oi];
        float r  = zq - zv;            // stop_gradient(z_q - z) value
        out[oi]  = zv + r;             // z + (z_q - z), fp32-rounded like ref
        lsum += (double)r * r;
    }
    #pragma unroll
    for (int o = 16; o; o >>= 1) lsum += __shfl_xor_sync(0xffffffffu, lsum, o);
    if (tt == 0) ssum[dp] = lsum;
    __syncthreads();
    if (tid == 0) {
        double tot = 0.0;
        #pragma unroll
        for (int p = 0; p < 8; p++) tot += ssum[p];
        atomicAdd(&g_loss, tot);
    }
}

__global__ void finalize_kernel(float* __restrict__ out, int out_size) {
    if (out_size >= ZQ_ELEMS + BT_ + 1)
        out[ZQ_ELEMS + BT_] =
            (float)(1.1 * g_loss / (double)ZQ_ELEMS);  // (1 + commitment_cost)*mse
}

// ---------------- launch ----------------
extern "C" void kernel_launch(void* const* d_in, const int* in_sizes, int n_in,
                              void* d_out, int out_size) {
    const float* z  = (const float*)d_in[0];
    const float* cb = (const float*)d_in[1];
    if (n_in >= 2 && in_sizes[0] == K_ * D_ && in_sizes[1] == ZQ_ELEMS) {
        const float* t = z; z = cb; cb = t;   // defensive input-order swap
    }
    float* out = (float*)d_out;

    init_kernel<<<(BT_ + 255) / 256, 256>>>();
    s2_kernel<<<(K_ * 32 + 255) / 256, 256>>>(cb);
    s1_kernel<<<BT_ / 32, 256>>>(z);

    dim3 grid(K_ / BN, BT_ / BM);   // (64, 128)
    dist_argmin_kernel<<<grid, 256>>>(z, cb);

    gather_kernel<<<BT_ / 32, 256>>>(z, cb, out, out_size);
    finalize_kernel<<<1, 1>>>(out, out_size);
}

// round 2
// speedup vs baseline: 1.0874x; 1.0874x over previous
#include <cuda_runtime.h>
#include <cstdint>

#define B_  8
#define D_  256
#define T_  2048
#define K_  8192
#define BT_ (B_ * T_)          // 16384 rows of z_flat
#define ZQ_ELEMS (BT_ * D_)    // 4194304

// ---------------- device scratch (no allocations allowed) ----------------
__device__ unsigned long long g_best[BT_];  // packed (orderedDist<<32 | idx)
__device__ float  g_s1[BT_];                // |z_m|^2
__device__ float  g_s2[K_];                 // |c_n|^2
__device__ double g_loss;

// ---------------- init ----------------
__global__ void init_kernel() {
    int i = blockIdx.x * blockDim.x + threadIdx.x;
    if (i < BT_) g_best[i] = 0xFFFFFFFFFFFFFFFFULL;
    if (i == 0)  g_loss = 0.0;
}

// ---------------- |c|^2 : one warp per code ----------------
__global__ void s2_kernel(const float* __restrict__ cb) {
    int warp = (blockIdx.x * blockDim.x + threadIdx.x) >> 5;
    int lane = threadIdx.x & 31;
    if (warp >= K_) return;
    const float* row = cb + (size_t)warp * D_;
    double s = 0.0;
    for (int d = lane; d < D_; d += 32) { float v = row[d]; s += (double)v * v; }
    #pragma unroll
    for (int o = 16; o; o >>= 1) s += __shfl_xor_sync(0xffffffffu, s, o);
    if (lane == 0) g_s2[warp] = (float)s;
}

// ---------------- |z_m|^2 : block handles 32 rows ----------------
__global__ void s1_kernel(const float* __restrict__ z) {
    __shared__ double sm[8][33];
    int m0 = blockIdx.x * 32;
    int b  = m0 >> 11;
    int t0 = m0 & 2047;
    int tt   = threadIdx.x & 31;
    int part = threadIdx.x >> 5;
    double s = 0.0;
    #pragma unroll 4
    for (int di = 0; di < 32; di++) {
        int d = part * 32 + di;
        float v = z[((size_t)b * D_ + d) * T_ + t0 + tt];
        s += (double)v * v;
    }
    sm[part][tt] = s;
    __syncthreads();
    if (part == 0) {
        double tot = 0.0;
        #pragma unroll
        for (int p = 0; p < 8; p++) tot += sm[p][tt];
        g_s1[m0 + tt] = (float)tot;
    }
}

// ---------------- distance GEMM + fused argmin ----------------
// CTA tile 256(m) x 128(n), BK=8, 256 threads, thread tile 16x8, packed FFMA2.
#define BM 256
#define BN 128
#define BK 8
#define BNP (BN + 4)           // padded Bs row

__device__ __forceinline__ unsigned long long pack2(float v) {
    unsigned long long r;
    asm("mov.b64 %0, {%1, %1};" : "=l"(r) : "f"(v));
    return r;
}
__device__ __forceinline__ void ffma2(unsigned long long& acc,
                                      unsigned long long a,
                                      unsigned long long b) {
    asm("fma.rn.f32x2 %0, %1, %2, %0;" : "+l"(acc) : "l"(a), "l"(b));
}

__global__ void __launch_bounds__(256)
dist_argmin_kernel(const float* __restrict__ z, const float* __restrict__ cb) {
    __shared__ float As[2][BK][BM];        // [kk][m]
    __shared__ float Bs[2][BK][BNP];       // [kk][n]

    int tid = threadIdx.x;
    int tx = tid & 15;                     // n-group 0..15
    int ty = tid >> 4;                     // m-group 0..15
    int m0 = blockIdx.y * BM;              // fixed b (BM=256 divides T)
    int n0 = blockIdx.x * BN;
    int b  = m0 >> 11;
    int t0 = m0 & 2047;

    const float* zb = z + (size_t)b * D_ * T_ + t0;
    // B load mapping: thread -> (n = tid>>1, q = tid&1), loads cb[n0+n][d0+4q..+3]
    int bn = tid >> 1, bq = tid & 1;
    const float* cbp = cb + (size_t)(n0 + bn) * D_ + bq * 4;

    unsigned long long acc[16][4];
    #pragma unroll
    for (int i = 0; i < 16; i++)
        #pragma unroll
        for (int p = 0; p < 4; p++) acc[i][p] = 0ULL;

    // ---- preload stage 0 ----
    {
        #pragma unroll
        for (int j = 0; j < 2; j++) {
            int f  = tid + j * 256;        // float4 slot 0..511
            int kk = f >> 6;               // 0..7
            int m4 = f & 63;               // 0..63
            float4 v = *reinterpret_cast<const float4*>(zb + (size_t)kk * T_ + m4 * 4);
            *reinterpret_cast<float4*>(&As[0][kk][m4 * 4]) = v;
        }
        float4 v = *reinterpret_cast<const float4*>(cbp);
        Bs[0][bq * 4 + 0][bn] = v.x;
        Bs[0][bq * 4 + 1][bn] = v.y;
        Bs[0][bq * 4 + 2][bn] = v.z;
        Bs[0][bq * 4 + 3][bn] = v.w;
    }
    __syncthreads();

    int buf = 0;
    for (int d0 = 0; d0 < D_; d0 += BK) {
        bool has_next = (d0 + BK) < D_;
        float4 pa0, pa1, pb;
        if (has_next) {
            int dn = d0 + BK;
            {
                int f = tid, kk = f >> 6, m4 = f & 63;
                pa0 = *reinterpret_cast<const float4*>(zb + (size_t)(dn + kk) * T_ + m4 * 4);
            }
            {
                int f = tid + 256, kk = f >> 6, m4 = f & 63;
                pa1 = *reinterpret_cast<const float4*>(zb + (size_t)(dn + kk) * T_ + m4 * 4);
            }
            pb = *reinterpret_cast<const float4*>(cbp + dn);
        }

        #pragma unroll
        for (int kk = 0; kk < BK; kk++) {
            float ra[16];
            #pragma unroll
            for (int q = 0; q < 4; q++)
                *reinterpret_cast<float4*>(&ra[q * 4]) =
                    *reinterpret_cast<const float4*>(&As[buf][kk][ty * 16 + q * 4]);
            unsigned long long rb[4];
            {
                const ulonglong2* bp =
                    reinterpret_cast<const ulonglong2*>(&Bs[buf][kk][tx * 8]);
                ulonglong2 b01 = bp[0];
                ulonglong2 b23 = bp[1];
                rb[0] = b01.x; rb[1] = b01.y; rb[2] = b23.x; rb[3] = b23.y;
            }
            #pragma unroll
            for (int i = 0; i < 16; i++) {
                unsigned long long ra2 = pack2(ra[i]);
                ffma2(acc[i][0], ra2, rb[0]);
                ffma2(acc[i][1], ra2, rb[1]);
                ffma2(acc[i][2], ra2, rb[2]);
                ffma2(acc[i][3], ra2, rb[3]);
            }
        }

        if (has_next) {
            int nb = buf ^ 1;
            {
                int f = tid, kk = f >> 6, m4 = f & 63;
                *reinterpret_cast<float4*>(&As[nb][kk][m4 * 4]) = pa0;
            }
            {
                int f = tid + 256, kk = f >> 6, m4 = f & 63;
                *reinterpret_cast<float4*>(&As[nb][kk][m4 * 4]) = pa1;
            }
            Bs[nb][bq * 4 + 0][bn] = pb.x;
            Bs[nb][bq * 4 + 1][bn] = pb.y;
            Bs[nb][bq * 4 + 2][bn] = pb.z;
            Bs[nb][bq * 4 + 3][bn] = pb.w;
        }
        __syncthreads();
        buf ^= 1;
    }

    // Epilogue: f = fl(fl(s1 - 2*dot) + s2) exactly as reference rounding grid.
    #pragma unroll
    for (int i = 0; i < 16; i++) {
        int m = m0 + ty * 16 + i;
        float s1 = g_s1[m];
        unsigned long long best = 0xFFFFFFFFFFFFFFFFULL;
        #pragma unroll
        for (int p = 0; p < 4; p++) {
            unsigned lo32 = (unsigned)(acc[i][p] & 0xFFFFFFFFULL);
            unsigned hi32 = (unsigned)(acc[i][p] >> 32);
            float d0v = __uint_as_float(lo32);
            float d1v = __uint_as_float(hi32);
            int n = n0 + tx * 8 + p * 2;
            {
                float f = (s1 - 2.0f * d0v) + g_s2[n];
                unsigned u = __float_as_uint(f);
                u = (u & 0x80000000u) ? ~u : (u | 0x80000000u);
                unsigned long long key = ((unsigned long long)u << 32) | (unsigned)n;
                best = best < key ? best : key;
            }
            {
                float f = (s1 - 2.0f * d1v) + g_s2[n + 1];
                unsigned u = __float_as_uint(f);
                u = (u & 0x80000000u) ? ~u : (u | 0x80000000u);
                unsigned long long key = ((unsigned long long)u << 32) | (unsigned)(n + 1);
                best = best < key ? best : key;
            }
        }
        // reduce across the 16 tx lanes sharing this row (xor<16 stays in ty group)
        #pragma unroll
        for (int o = 8; o; o >>= 1) {
            unsigned long long other = __shfl_xor_sync(0xffffffffu, best, o);
            best = best < other ? best : other;
        }
        if (tx == 0) atomicMin(&g_best[m], best);
    }
}

// ---------------- gather z_q_st (transposed), indices, loss ----------------
__global__ void gather_kernel(const float* __restrict__ z,
                              const float* __restrict__ cb,
                              float* __restrict__ out, int out_size) {
    __shared__ float sm[32][257];
    __shared__ int   sidx[32];
    __shared__ double ssum[8];
    int m0 = blockIdx.x * 32;
    int b  = m0 >> 11;
    int t0 = m0 & 2047;
    int tid = threadIdx.x;

    if (tid < 32) {
        int idx = (int)(g_best[m0 + tid] & 0xFFFFFFFFULL);
        sidx[tid] = idx;
        if (out_size >= ZQ_ELEMS + BT_)
            out[ZQ_ELEMS + m0 + tid] = (float)idx;
    }
    __syncthreads();

    for (int r = 0; r < 32; r++)
        sm[r][tid] = cb[(size_t)sidx[r] * D_ + tid];
    __syncthreads();

    int tt = tid & 31;
    int dp = tid >> 5;
    double lsum = 0.0;
    #pragma unroll 4
    for (int it = 0; it < 32; it++) {
        int d = dp * 32 + it;
        size_t oi = ((size_t)b * D_ + d) * T_ + t0 + tt;
        float zq = sm[tt][d];
        float zv = z[oi];
        float r  = zq - zv;
        out[oi]  = zv + r;
        lsum += (double)r * r;
    }
    #pragma unroll
    for (int o = 16; o; o >>= 1) lsum += __shfl_xor_sync(0xffffffffu, lsum, o);
    if (tt == 0) ssum[dp] = lsum;
    __syncthreads();
    if (tid == 0) {
        double tot = 0.0;
        #pragma unroll
        for (int p = 0; p < 8; p++) tot += ssum[p];
        atomicAdd(&g_loss, tot);
    }
}

__global__ void finalize_kernel(float* __restrict__ out, int out_size) {
    if (out_size >= ZQ_ELEMS + BT_ + 1)
        out[ZQ_ELEMS + BT_] =
            (float)(1.1 * g_loss / (double)ZQ_ELEMS);
}

// ---------------- launch ----------------
extern "C" void kernel_launch(void* const* d_in, const int* in_sizes, int n_in,
                              void* d_out, int out_size) {
    const float* z  = (const float*)d_in[0];
    const float* cb = (const float*)d_in[1];
    if (n_in >= 2 && in_sizes[0] == K_ * D_ && in_sizes[1] == ZQ_ELEMS) {
        const float* t = z; z = cb; cb = t;
    }
    float* out = (float*)d_out;

    init_kernel<<<(BT_ + 255) / 256, 256>>>();
    s2_kernel<<<(K_ * 32 + 255) / 256, 256>>>(cb);
    s1_kernel<<<BT_ / 32, 256>>>(z);

    dim3 grid(K_ / BN, BT_ / BM);   // (64, 64)
    dist_argmin_kernel<<<grid, 256>>>(z, cb);

    gather_kernel<<<BT_ / 32, 256>>>(z, cb, out, out_size);
    finalize_kernel<<<1, 1>>>(out, out_size);
}